// round 7
// baseline (speedup 1.0000x reference)
#include <cuda_runtime.h>
#include <cfloat>

#define MAX_PINS 7000000

// 56 MB interleaved coordinate scratch (device globals are the sanctioned
// no-alloc scratch mechanism).
__device__ float2 g_xy[MAX_PINS];

// Self-restoring accumulator state (zero-init at load; last block restores).
__device__ double g_hpwl_accum = 0.0;
__device__ unsigned int g_block_count = 0u;

// Kernel 1: interleave pos[x-half], pos[y-half] -> float2 (coalesced stream).
// 2 pins per thread per iteration for extra MLP on the streaming loads.
__global__ void __launch_bounds__(256) interleave_kernel(
    const float* __restrict__ pos, int num_pins)
{
    const int stride = gridDim.x * blockDim.x;
    int p = blockIdx.x * blockDim.x + threadIdx.x;
    for (; p + stride < num_pins; p += 2 * stride) {
        const int p2 = p + stride;
        const float x0 = __ldg(pos + p);
        const float x1 = __ldg(pos + p2);
        const float y0 = __ldg(pos + num_pins + p);
        const float y1 = __ldg(pos + num_pins + p2);
        g_xy[p]  = make_float2(x0, y0);
        g_xy[p2] = make_float2(x1, y1);
    }
    if (p < num_pins) {
        g_xy[p] = make_float2(__ldg(pos + p), __ldg(pos + num_pins + p));
    }
}

// Kernel 2: net-per-thread HPWL over interleaved coords (one 8B gather/pin).
template <bool USE_XY>
__global__ void __launch_bounds__(256) hpwl_kernel(
    const float* __restrict__ pos,
    const int* __restrict__ flat_netpin,
    const int* __restrict__ netpin_start,
    const int* __restrict__ ignore_ptr,
    int num_nets, int num_pins,
    float* __restrict__ out,
    unsigned int total_blocks)
{
    __shared__ float s_warp[8];
    const int i = blockIdx.x * blockDim.x + threadIdx.x;
    const int ignore_deg = *ignore_ptr;

    float local = 0.0f;
    if (i < num_nets) {
        const int s = netpin_start[i];
        const int e = netpin_start[i + 1];
        const int deg = e - s;
        if (deg > 0 && deg <= ignore_deg) {
            float xmin = FLT_MAX, xmax = -FLT_MAX;
            float ymin = FLT_MAX, ymax = -FLT_MAX;
            #pragma unroll
            for (int k = 0; k < 8; ++k) {
                if (k < deg) {
                    const int p = __ldg(flat_netpin + s + k);
                    float x, y;
                    if (USE_XY) {
                        const float2 xy = g_xy[p];
                        x = xy.x; y = xy.y;
                    } else {
                        x = __ldg(pos + p);
                        y = __ldg(pos + num_pins + p);
                    }
                    xmin = fminf(xmin, x);
                    xmax = fmaxf(xmax, x);
                    ymin = fminf(ymin, y);
                    ymax = fmaxf(ymax, y);
                }
            }
            local = (xmax - xmin) + (ymax - ymin);
        }
    }

    #pragma unroll
    for (int off = 16; off > 0; off >>= 1)
        local += __shfl_down_sync(0xFFFFFFFFu, local, off);

    const int lane = threadIdx.x & 31;
    const int wid  = threadIdx.x >> 5;
    if (lane == 0) s_warp[wid] = local;
    __syncthreads();

    if (wid == 0) {
        float v = (lane < 8) ? s_warp[lane] : 0.0f;
        #pragma unroll
        for (int off = 4; off > 0; off >>= 1)
            v += __shfl_down_sync(0xFFFFFFFFu, v, off);

        if (lane == 0) {
            atomicAdd(&g_hpwl_accum, (double)v);
            __threadfence();
            const unsigned int done = atomicAdd(&g_block_count, 1u);
            if (done == total_blocks - 1) {
                out[0] = (float)g_hpwl_accum;
                g_hpwl_accum = 0.0;
                g_block_count = 0u;
            }
        }
    }
}

extern "C" void kernel_launch(void* const* d_in, const int* in_sizes, int n_in,
                              void* d_out, int out_size)
{
    const float* pos       = (const float*)d_in[0];
    const int* flat        = (const int*)d_in[1];
    const int* start       = (const int*)d_in[2];
    const int* ignore_ptr  = (const int*)d_in[3];

    const int num_pins = in_sizes[1];
    const int num_nets = in_sizes[2] - 1;

    const int threads = 256;
    const unsigned int blocks = (num_nets + threads - 1) / threads;

    if (num_pins <= MAX_PINS) {
        // Pre-pass: coalesced interleave (full-chip grid-stride).
        const int iblocks = 148 * 8;
        interleave_kernel<<<iblocks, threads>>>(pos, num_pins);
        hpwl_kernel<true><<<blocks, threads>>>(pos, flat, start, ignore_ptr,
                                               num_nets, num_pins,
                                               (float*)d_out, blocks);
    } else {
        hpwl_kernel<false><<<blocks, threads>>>(pos, flat, start, ignore_ptr,
                                                num_nets, num_pins,
                                                (float*)d_out, blocks);
    }
}

// round 13
// speedup vs baseline: 1.1247x; 1.1247x over previous
#include <cuda_runtime.h>
#include <cuda_fp16.h>
#include <cfloat>

#define MAX_PINS 7000000

// 28 MB packed-coordinate scratch: one half2 per pin = (x, y).
__device__ __half2 g_xyh[MAX_PINS];

// Self-restoring accumulator state (zero-init at load; last block restores).
__device__ double g_hpwl_accum = 0.0;
__device__ unsigned int g_block_count = 0u;

// Kernel 1: pack pos[x-half], pos[y-half] -> half2 per pin (coalesced stream).
// Each thread handles 2 pins via float2 loads + one 8B store.
__global__ void __launch_bounds__(256) pack_kernel(
    const float* __restrict__ pos, int num_pins)
{
    const int half_n = num_pins >> 1;
    const int i = blockIdx.x * blockDim.x + threadIdx.x;
    if (i < half_n) {
        const float2 xv = __ldg((const float2*)pos + i);
        const float2 yv = __ldg((const float2*)(pos + num_pins) + i);
        __half2 h0 = __floats2half2_rn(xv.x, yv.x);  // pin 2i
        __half2 h1 = __floats2half2_rn(xv.y, yv.y);  // pin 2i+1
        uint2 packed;
        packed.x = *reinterpret_cast<unsigned int*>(&h0);
        packed.y = *reinterpret_cast<unsigned int*>(&h1);
        reinterpret_cast<uint2*>(g_xyh)[i] = packed;
    }
    // Odd tail
    if (i == 0 && (num_pins & 1)) {
        const int p = num_pins - 1;
        g_xyh[p] = __floats2half2_rn(__ldg(pos + p), __ldg(pos + num_pins + p));
    }
}

// Kernel 2: net-per-thread HPWL; one 4B gather per pin.
template <bool USE_PACKED>
__global__ void __launch_bounds__(256) hpwl_kernel(
    const float* __restrict__ pos,
    const int* __restrict__ flat_netpin,
    const int* __restrict__ netpin_start,
    const int* __restrict__ ignore_ptr,
    int num_nets, int num_pins,
    float* __restrict__ out,
    unsigned int total_blocks)
{
    __shared__ float s_warp[8];
    const int i = blockIdx.x * blockDim.x + threadIdx.x;
    const int ignore_deg = *ignore_ptr;

    float local = 0.0f;
    if (i < num_nets) {
        const int s = netpin_start[i];
        const int e = netpin_start[i + 1];
        const int deg = e - s;
        if (deg > 0 && deg <= ignore_deg) {
            float xmin = FLT_MAX, xmax = -FLT_MAX;
            float ymin = FLT_MAX, ymax = -FLT_MAX;
            #pragma unroll
            for (int k = 0; k < 8; ++k) {
                if (k < deg) {
                    const int p = __ldg(flat_netpin + s + k);
                    float x, y;
                    if (USE_PACKED) {
                        const float2 f = __half22float2(g_xyh[p]);
                        x = f.x; y = f.y;
                    } else {
                        x = __ldg(pos + p);
                        y = __ldg(pos + num_pins + p);
                    }
                    xmin = fminf(xmin, x);
                    xmax = fmaxf(xmax, x);
                    ymin = fminf(ymin, y);
                    ymax = fmaxf(ymax, y);
                }
            }
            local = (xmax - xmin) + (ymax - ymin);
        }
    }

    #pragma unroll
    for (int off = 16; off > 0; off >>= 1)
        local += __shfl_down_sync(0xFFFFFFFFu, local, off);

    const int lane = threadIdx.x & 31;
    const int wid  = threadIdx.x >> 5;
    if (lane == 0) s_warp[wid] = local;
    __syncthreads();

    if (wid == 0) {
        float v = (lane < 8) ? s_warp[lane] : 0.0f;
        #pragma unroll
        for (int off = 4; off > 0; off >>= 1)
            v += __shfl_down_sync(0xFFFFFFFFu, v, off);

        if (lane == 0) {
            atomicAdd(&g_hpwl_accum, (double)v);
            __threadfence();
            const unsigned int done = atomicAdd(&g_block_count, 1u);
            if (done == total_blocks - 1) {
                out[0] = (float)g_hpwl_accum;
                g_hpwl_accum = 0.0;
                g_block_count = 0u;
            }
        }
    }
}

extern "C" void kernel_launch(void* const* d_in, const int* in_sizes, int n_in,
                              void* d_out, int out_size)
{
    const float* pos       = (const float*)d_in[0];
    const int* flat        = (const int*)d_in[1];
    const int* start       = (const int*)d_in[2];
    const int* ignore_ptr  = (const int*)d_in[3];

    const int num_pins = in_sizes[1];
    const int num_nets = in_sizes[2] - 1;

    const int threads = 256;
    const unsigned int blocks = (num_nets + threads - 1) / threads;

    if (num_pins <= MAX_PINS) {
        const int half_n = num_pins >> 1;
        const int pblocks = (half_n + threads - 1) / threads;
        pack_kernel<<<pblocks > 0 ? pblocks : 1, threads>>>(pos, num_pins);
        hpwl_kernel<true><<<blocks, threads>>>(pos, flat, start, ignore_ptr,
                                               num_nets, num_pins,
                                               (float*)d_out, blocks);
    } else {
        hpwl_kernel<false><<<blocks, threads>>>(pos, flat, start, ignore_ptr,
                                                num_nets, num_pins,
                                                (float*)d_out, blocks);
    }
}

// round 17
// speedup vs baseline: 1.1908x; 1.0587x over previous
#include <cuda_runtime.h>
#include <cuda_fp16.h>
#include <cfloat>

#define MAX_PINS 7000000

// 28 MB packed-coordinate scratch: one half2 per pin = (x, y).
__device__ __half2 g_xyh[MAX_PINS];

// Self-restoring accumulator state (zero-init at load; last block restores).
__device__ double g_hpwl_accum = 0.0;
__device__ unsigned int g_block_count = 0u;

// Kernel 1: pack pos -> half2/pin. pos reads use evict-first streaming (__ldcs)
// so they don't evict the scratch we are writing (which the gather re-reads).
// 4 pins per thread: float4 loads + one 16B store.
__global__ void __launch_bounds__(256) pack_kernel(
    const float* __restrict__ pos, int num_pins)
{
    const int quarter_n = num_pins >> 2;
    const int i = blockIdx.x * blockDim.x + threadIdx.x;
    if (i < quarter_n) {
        const float4 xv = __ldcs((const float4*)pos + i);
        const float4 yv = __ldcs((const float4*)(pos + num_pins) + i);
        __half2 h0 = __floats2half2_rn(xv.x, yv.x);
        __half2 h1 = __floats2half2_rn(xv.y, yv.y);
        __half2 h2 = __floats2half2_rn(xv.z, yv.z);
        __half2 h3 = __floats2half2_rn(xv.w, yv.w);
        uint4 packed;
        packed.x = *reinterpret_cast<unsigned int*>(&h0);
        packed.y = *reinterpret_cast<unsigned int*>(&h1);
        packed.z = *reinterpret_cast<unsigned int*>(&h2);
        packed.w = *reinterpret_cast<unsigned int*>(&h3);
        reinterpret_cast<uint4*>(g_xyh)[i] = packed;
    }
    // Tail (num_pins % 4 pins)
    if (i == 0) {
        for (int p = quarter_n << 2; p < num_pins; ++p) {
            g_xyh[p] = __floats2half2_rn(__ldcs(pos + p),
                                         __ldcs(pos + num_pins + p));
        }
    }
}

// Kernel 2: net-per-thread HPWL; one 4B gather per pin. Index streams use
// __ldcs (no reuse) to preserve L2 residency of g_xyh.
template <bool USE_PACKED>
__global__ void __launch_bounds__(256) hpwl_kernel(
    const float* __restrict__ pos,
    const int* __restrict__ flat_netpin,
    const int* __restrict__ netpin_start,
    const int* __restrict__ ignore_ptr,
    int num_nets, int num_pins,
    float* __restrict__ out,
    unsigned int total_blocks)
{
    __shared__ float s_warp[8];
    const int i = blockIdx.x * blockDim.x + threadIdx.x;
    const int ignore_deg = *ignore_ptr;

    float local = 0.0f;
    if (i < num_nets) {
        const int s = __ldcs(netpin_start + i);
        const int e = __ldcs(netpin_start + i + 1);
        const int deg = e - s;
        if (deg > 0 && deg <= ignore_deg) {
            float xmin = FLT_MAX, xmax = -FLT_MAX;
            float ymin = FLT_MAX, ymax = -FLT_MAX;
            #pragma unroll
            for (int k = 0; k < 8; ++k) {
                if (k < deg) {
                    const int p = __ldcs(flat_netpin + s + k);
                    float x, y;
                    if (USE_PACKED) {
                        const float2 f = __half22float2(g_xyh[p]);
                        x = f.x; y = f.y;
                    } else {
                        x = __ldg(pos + p);
                        y = __ldg(pos + num_pins + p);
                    }
                    xmin = fminf(xmin, x);
                    xmax = fmaxf(xmax, x);
                    ymin = fminf(ymin, y);
                    ymax = fmaxf(ymax, y);
                }
            }
            local = (xmax - xmin) + (ymax - ymin);
        }
    }

    #pragma unroll
    for (int off = 16; off > 0; off >>= 1)
        local += __shfl_down_sync(0xFFFFFFFFu, local, off);

    const int lane = threadIdx.x & 31;
    const int wid  = threadIdx.x >> 5;
    if (lane == 0) s_warp[wid] = local;
    __syncthreads();

    if (wid == 0) {
        float v = (lane < 8) ? s_warp[lane] : 0.0f;
        #pragma unroll
        for (int off = 4; off > 0; off >>= 1)
            v += __shfl_down_sync(0xFFFFFFFFu, v, off);

        if (lane == 0) {
            atomicAdd(&g_hpwl_accum, (double)v);
            __threadfence();
            const unsigned int done = atomicAdd(&g_block_count, 1u);
            if (done == total_blocks - 1) {
                out[0] = (float)g_hpwl_accum;
                g_hpwl_accum = 0.0;
                g_block_count = 0u;
            }
        }
    }
}

extern "C" void kernel_launch(void* const* d_in, const int* in_sizes, int n_in,
                              void* d_out, int out_size)
{
    const float* pos       = (const float*)d_in[0];
    const int* flat        = (const int*)d_in[1];
    const int* start       = (const int*)d_in[2];
    const int* ignore_ptr  = (const int*)d_in[3];

    const int num_pins = in_sizes[1];
    const int num_nets = in_sizes[2] - 1;

    const int threads = 256;
    const unsigned int blocks = (num_nets + threads - 1) / threads;

    if (num_pins <= MAX_PINS) {
        const int quarter_n = num_pins >> 2;
        const int pblocks = (quarter_n + threads - 1) / threads;
        pack_kernel<<<pblocks > 0 ? pblocks : 1, threads>>>(pos, num_pins);
        hpwl_kernel<true><<<blocks, threads>>>(pos, flat, start, ignore_ptr,
                                               num_nets, num_pins,
                                               (float*)d_out, blocks);
    } else {
        hpwl_kernel<false><<<blocks, threads>>>(pos, flat, start, ignore_ptr,
                                                num_nets, num_pins,
                                                (float*)d_out, blocks);
    }
}